// round 6
// baseline (speedup 1.0000x reference)
#include <cuda_runtime.h>
#include <cuda_bf16.h>
#include <math.h>

#define NFEAT   256
#define NHID    64
#define NCLASS  16
#define MAXN    50000
#define MAXE    1600000

typedef unsigned long long ull;

// ---------------------------------------------------------------------------
// Scratch (allocation-free device globals)
// ---------------------------------------------------------------------------
__device__ __align__(16) float g_S1[MAXN * NHID];     // x @ W1
__device__ __align__(16) float g_H [MAXN * NHID];     // spmm1 + b1
__device__ __align__(16) float g_S2[MAXN * NCLASS];   // relu(H) @ W2

__device__ int   g_cnt[MAXN];        // in-degree per dst
__device__ int   g_off[MAXN];        // CSR row offsets (exclusive scan of cnt)
__device__ int   g_cur[MAXN];        // scatter cursors
__device__ int   g_blksum[256];      // scan partials
__device__ __align__(8) int   g_csr_src[MAXE];
__device__ __align__(8) float g_csr_w [MAXE];

// ---------------------------------------------------------------------------
// f32x2 packed-FMA helpers (sm_100+ PTX; ptxas never auto-fuses these)
// ---------------------------------------------------------------------------
__device__ __forceinline__ ull fma2(ull a, ull b, ull c) {
    ull d;
    asm("fma.rn.f32x2 %0, %1, %2, %3;" : "=l"(d) : "l"(a), "l"(b), "l"(c));
    return d;
}
__device__ __forceinline__ ull pack2(float x) {
    ull d; unsigned int u = __float_as_uint(x);
    asm("mov.b64 %0, {%1, %2};" : "=l"(d) : "r"(u), "r"(u));
    return d;
}

// ---------------------------------------------------------------------------
// GEMM1: S1[N,64] = x[N,256] @ W1[256,64]
// 64x64 tile, 256 threads, 2 rows x 8 cols per thread, FFMA2 inner.
// ---------------------------------------------------------------------------
__global__ void __launch_bounds__(256) gemm1_kernel(
    const float* __restrict__ x, const float* __restrict__ W1, int n_nodes)
{
    __shared__ float xs[64][33];
    __shared__ float ws[32][64];

    const int tid = threadIdx.x;
    const int tx = tid & 7;          // col group: 8 cols at 8*tx
    const int ty = tid >> 3;         // rows {ty, ty+32}
    const int rowBase = blockIdx.x * 64;

    ull acc0[4], acc1[4];            // 2 rows x 4 col-pairs
#pragma unroll
    for (int p = 0; p < 4; p++) { acc0[p] = 0ull; acc1[p] = 0ull; }

#pragma unroll 1
    for (int k0 = 0; k0 < NFEAT; k0 += 32) {
#pragma unroll
        for (int j = 0; j < 2; j++) {
            int s = tid * 2 + j;               // 0..511
            int r = s >> 3;                    // 0..63
            int c4 = s & 7;                    // 0..7
            float4 v = make_float4(0.f, 0.f, 0.f, 0.f);
            int grow = rowBase + r;
            if (grow < n_nodes)
                v = *reinterpret_cast<const float4*>(&x[grow * NFEAT + k0 + c4 * 4]);
            xs[r][c4 * 4 + 0] = v.x; xs[r][c4 * 4 + 1] = v.y;
            xs[r][c4 * 4 + 2] = v.z; xs[r][c4 * 4 + 3] = v.w;
        }
#pragma unroll
        for (int j = 0; j < 2; j++) {
            int s = tid * 2 + j;
            int kk = s >> 4;
            int c4 = s & 15;
            float4 v = *reinterpret_cast<const float4*>(&W1[(k0 + kk) * NHID + c4 * 4]);
            *reinterpret_cast<float4*>(&ws[kk][c4 * 4]) = v;
        }
        __syncthreads();

#pragma unroll
        for (int kk = 0; kk < 32; kk++) {
            ull a0 = pack2(xs[ty][kk]);
            ull a1 = pack2(xs[ty + 32][kk]);
            ulonglong2 w01 = *reinterpret_cast<const ulonglong2*>(&ws[kk][8 * tx]);
            ulonglong2 w23 = *reinterpret_cast<const ulonglong2*>(&ws[kk][8 * tx + 4]);
            acc0[0] = fma2(a0, w01.x, acc0[0]);
            acc0[1] = fma2(a0, w01.y, acc0[1]);
            acc0[2] = fma2(a0, w23.x, acc0[2]);
            acc0[3] = fma2(a0, w23.y, acc0[3]);
            acc1[0] = fma2(a1, w01.x, acc1[0]);
            acc1[1] = fma2(a1, w01.y, acc1[1]);
            acc1[2] = fma2(a1, w23.x, acc1[2]);
            acc1[3] = fma2(a1, w23.y, acc1[3]);
        }
        __syncthreads();
    }

    int r0 = rowBase + ty, r1 = rowBase + ty + 32;
    if (r0 < n_nodes) {
#pragma unroll
        for (int p = 0; p < 4; p++)
            *reinterpret_cast<ull*>(&g_S1[r0 * NHID + 8 * tx + 2 * p]) = acc0[p];
    }
    if (r1 < n_nodes) {
#pragma unroll
        for (int p = 0; p < 4; p++)
            *reinterpret_cast<ull*>(&g_S1[r1 * NHID + 8 * tx + 2 * p]) = acc1[p];
    }
}

// ---------------------------------------------------------------------------
// CSR build: zero -> histogram -> scan (3 stages) -> scatter
// ---------------------------------------------------------------------------
__global__ void zero_cnt_kernel(int n)
{
    int i = blockIdx.x * blockDim.x + threadIdx.x;
    if (i < n) g_cnt[i] = 0;
}

__global__ void hist_kernel(const int* __restrict__ dst, int n_edges)
{
    int e = blockIdx.x * blockDim.x + threadIdx.x;
    if (e < n_edges) atomicAdd(&g_cnt[dst[e]], 1);
}

__global__ void __launch_bounds__(512) scan_part_kernel(int n)
{
    __shared__ int wsum[16];
    int i = blockIdx.x * 512 + threadIdx.x;
    int lane = threadIdx.x & 31, wid = threadIdx.x >> 5;
    int v = (i < n) ? g_cnt[i] : 0;
    int x = v;
#pragma unroll
    for (int o = 1; o < 32; o <<= 1) {
        int t = __shfl_up_sync(0xffffffffu, x, o);
        if (lane >= o) x += t;
    }
    if (lane == 31) wsum[wid] = x;
    __syncthreads();
    if (wid == 0) {
        int s = (lane < 16) ? wsum[lane] : 0;
#pragma unroll
        for (int o = 1; o < 16; o <<= 1) {
            int t = __shfl_up_sync(0xffffffffu, s, o);
            if (lane >= o) s += t;
        }
        if (lane < 16) wsum[lane] = s;
    }
    __syncthreads();
    int base = (wid > 0) ? wsum[wid - 1] : 0;
    int excl = base + x - v;
    if (i < n) g_off[i] = excl;
    if (threadIdx.x == 511) g_blksum[blockIdx.x] = base + x;
}

__global__ void scan_block_kernel(int nb)
{
    int run = 0;
    for (int j = 0; j < nb; j++) { int t = g_blksum[j]; g_blksum[j] = run; run += t; }
}

__global__ void scan_add_kernel(int n)
{
    int i = blockIdx.x * blockDim.x + threadIdx.x;
    if (i < n) {
        int o = g_off[i] + g_blksum[i >> 9];
        g_off[i] = o;
        g_cur[i] = o;
    }
}

__global__ void scatter_kernel(
    const int* __restrict__ src, const int* __restrict__ dst,
    const float* __restrict__ ew, int n_edges)
{
    int e = blockIdx.x * blockDim.x + threadIdx.x;
    if (e < n_edges) {
        int d = dst[e];
        int p = atomicAdd(&g_cur[d], 1);
        g_csr_src[p] = src[e];
        g_csr_w[p]  = ew[e];
    }
}

// ---------------------------------------------------------------------------
// SpMM1 (pull): H[d] = b1 + sum_e w_e * S1[src_e]   — warp per dst, no atomics
// Each lane owns 2 features (64-bit), FFMA2 accumulate.
// ---------------------------------------------------------------------------
__global__ void __launch_bounds__(256) spmm1_pull_kernel(
    const float* __restrict__ b1, int n_nodes)
{
    int lane = threadIdx.x & 31;
    int d = blockIdx.x * 8 + (threadIdx.x >> 5);
    if (d >= n_nodes) return;

    ull acc = *reinterpret_cast<const ull*>(&b1[2 * lane]);
    int beg = g_off[d];
    int end = beg + g_cnt[d];

    int j = beg;
    for (; j + 1 < end; j += 2) {
        int   s0 = g_csr_src[j],     s1 = g_csr_src[j + 1];
        float w0 = g_csr_w[j],       w1 = g_csr_w[j + 1];
        ull v0 = *reinterpret_cast<const ull*>(&g_S1[s0 * NHID + 2 * lane]);
        ull v1 = *reinterpret_cast<const ull*>(&g_S1[s1 * NHID + 2 * lane]);
        acc = fma2(pack2(w0), v0, acc);
        acc = fma2(pack2(w1), v1, acc);
    }
    if (j < end) {
        int s = g_csr_src[j];
        float w = g_csr_w[j];
        ull v = *reinterpret_cast<const ull*>(&g_S1[s * NHID + 2 * lane]);
        acc = fma2(pack2(w), v, acc);
    }
    *reinterpret_cast<ull*>(&g_H[d * NHID + 2 * lane]) = acc;
}

// ---------------------------------------------------------------------------
// GEMM2 fused ReLU: S2[N,16] = relu(H)[N,64] @ W2[64,16]
// 128x16 tile, 256 threads, 2 rows x 4 cols per thread, FFMA2 inner.
// ---------------------------------------------------------------------------
__global__ void __launch_bounds__(256) gemm2_kernel(
    const float* __restrict__ W2, int n_nodes)
{
    __shared__ float hs[128][68];    // 68: pad, keeps float4 alignment
    __shared__ float ws2[64][16];

    const int tid = threadIdx.x;
    const int tx = tid & 3;          // 4 cols at 4*tx
    const int ty = tid >> 2;         // rows {ty, ty+64}
    const int rowBase = blockIdx.x * 128;

    // Load H tile with ReLU: 128 rows x 16 float4 = 2048 slots, 8 per thread
#pragma unroll
    for (int j = 0; j < 8; j++) {
        int s = tid + j * 256;
        int r = s >> 4;
        int c4 = s & 15;
        float4 v = make_float4(0.f, 0.f, 0.f, 0.f);
        int grow = rowBase + r;
        if (grow < n_nodes)
            v = *reinterpret_cast<const float4*>(&g_H[grow * NHID + c4 * 4]);
        v.x = fmaxf(v.x, 0.f); v.y = fmaxf(v.y, 0.f);
        v.z = fmaxf(v.z, 0.f); v.w = fmaxf(v.w, 0.f);
        *reinterpret_cast<float4*>(&hs[r][c4 * 4]) = v;
    }
    // Load W2: 64x16 = 256 float4, 1 per thread
    {
        int kk = tid >> 2;
        int c4 = tid & 3;
        float4 v = *reinterpret_cast<const float4*>(&W2[kk * NCLASS + c4 * 4]);
        *reinterpret_cast<float4*>(&ws2[kk][c4 * 4]) = v;
    }
    __syncthreads();

    ull acc0[2] = {0ull, 0ull};
    ull acc1[2] = {0ull, 0ull};
#pragma unroll
    for (int kk = 0; kk < NHID; kk++) {
        ull a0 = pack2(hs[ty][kk]);
        ull a1 = pack2(hs[ty + 64][kk]);
        ulonglong2 w = *reinterpret_cast<const ulonglong2*>(&ws2[kk][4 * tx]);
        acc0[0] = fma2(a0, w.x, acc0[0]);
        acc0[1] = fma2(a0, w.y, acc0[1]);
        acc1[0] = fma2(a1, w.x, acc1[0]);
        acc1[1] = fma2(a1, w.y, acc1[1]);
    }

    int r0 = rowBase + ty, r1 = rowBase + ty + 64;
    if (r0 < n_nodes) {
        *reinterpret_cast<ull*>(&g_S2[r0 * NCLASS + 4 * tx])     = acc0[0];
        *reinterpret_cast<ull*>(&g_S2[r0 * NCLASS + 4 * tx + 2]) = acc0[1];
    }
    if (r1 < n_nodes) {
        *reinterpret_cast<ull*>(&g_S2[r1 * NCLASS + 4 * tx])     = acc1[0];
        *reinterpret_cast<ull*>(&g_S2[r1 * NCLASS + 4 * tx + 2]) = acc1[1];
    }
}

// ---------------------------------------------------------------------------
// SpMM2 (pull) + bias + log_softmax fused: out[d] = lsm(b2 + sum w*S2[src])
// 16 lanes per dst (1 class each); shfl-based max/sum within the 16-group.
// ---------------------------------------------------------------------------
__global__ void __launch_bounds__(256) spmm2_lsm_kernel(
    const float* __restrict__ b2, float* __restrict__ out, int n_nodes)
{
    int lane16 = threadIdx.x & 15;
    int d = blockIdx.x * 16 + (threadIdx.x >> 4);
    if (d >= n_nodes) return;

    float acc = b2[lane16];
    int beg = g_off[d];
    int end = beg + g_cnt[d];

    int j = beg;
    for (; j + 1 < end; j += 2) {
        int   s0 = g_csr_src[j],  s1 = g_csr_src[j + 1];
        float w0 = g_csr_w[j],    w1 = g_csr_w[j + 1];
        float v0 = g_S2[s0 * NCLASS + lane16];
        float v1 = g_S2[s1 * NCLASS + lane16];
        acc = fmaf(w0, v0, acc);
        acc = fmaf(w1, v1, acc);
    }
    if (j < end) {
        int s = g_csr_src[j];
        acc = fmaf(g_csr_w[j], g_S2[s * NCLASS + lane16], acc);
    }

    // log_softmax over the 16-lane group
    float m = acc;
#pragma unroll
    for (int o = 8; o >= 1; o >>= 1)
        m = fmaxf(m, __shfl_xor_sync(0xffffffffu, m, o, 16));
    float e = expf(acc - m);
    float ssum = e;
#pragma unroll
    for (int o = 8; o >= 1; o >>= 1)
        ssum += __shfl_xor_sync(0xffffffffu, ssum, o, 16);
    out[d * NCLASS + lane16] = acc - m - logf(ssum);
}

// ---------------------------------------------------------------------------
// Launch.  Inputs: x, W1, b1, W2, b2, edge_src, edge_dst, edge_weight
// ---------------------------------------------------------------------------
extern "C" void kernel_launch(void* const* d_in, const int* in_sizes, int n_in,
                              void* d_out, int out_size)
{
    const float* x    = (const float*)d_in[0];
    const float* W1   = (const float*)d_in[1];
    const float* b1   = (const float*)d_in[2];
    const float* W2   = (const float*)d_in[3];
    const float* b2   = (const float*)d_in[4];
    const int*   esrc = (const int*)d_in[5];
    const int*   edst = (const int*)d_in[6];
    const float* ew   = (const float*)d_in[7];

    int n_nodes = in_sizes[0] / NFEAT;
    int n_edges = in_sizes[5];
    int nb = (n_nodes + 511) / 512;

    // GEMM1 (independent of CSR build)
    gemm1_kernel<<<(n_nodes + 63) / 64, 256>>>(x, W1, n_nodes);

    // CSR-by-dst build
    zero_cnt_kernel<<<(n_nodes + 255) / 256, 256>>>(n_nodes);
    hist_kernel<<<(n_edges + 255) / 256, 256>>>(edst, n_edges);
    scan_part_kernel<<<nb, 512>>>(n_nodes);
    scan_block_kernel<<<1, 1>>>(nb);
    scan_add_kernel<<<(n_nodes + 255) / 256, 256>>>(n_nodes);
    scatter_kernel<<<(n_edges + 255) / 256, 256>>>(esrc, edst, ew, n_edges);

    // Layer 1 aggregate (pull, warp/dst)
    spmm1_pull_kernel<<<(n_nodes + 7) / 8, 256>>>(b1, n_nodes);

    // Layer 2
    gemm2_kernel<<<(n_nodes + 127) / 128, 256>>>(W2, n_nodes);
    spmm2_lsm_kernel<<<(n_nodes + 15) / 16, 256>>>(b2, (float*)d_out, n_nodes);
}